// round 11
// baseline (speedup 1.0000x reference)
#include <cuda_runtime.h>

// Problem constants (fixed by the dataset)
#define B   4
#define P   12000
#define NF  64
#define XS  512
#define YS  512
#define CELLS    (XS * YS)                // 262144 per batch
#define BP_TOTAL (B * P)                  // 48000
#define SPANS    256                      // 1024-cell spans per batch
#define LIST_MAX 128                      // >> mean 23.4 touched/span
#define CHUNKS   32                       // 32KB chunks per plane (8 spans each)

// Epoch-tagged slot map: value = (epoch<<17) | (bp+1); epoch in [1,32767].
// Entries written in a previous call parse as empty -> no 4 MB init needed.
__device__ unsigned g_epoch;                      // current tag (0 at load)
__device__ unsigned g_slot[B * CELLS];            // 4 MB
__device__ int      g_next[BP_TOTAL];             // chain next, -1 terminated
__device__ unsigned g_cnt[B * SPANS];             // touched cells per span
__device__ int      g_list[B * SPANS * LIST_MAX]; // touched cell ids (512 KB)

// ---------------------------------------------------------------------------
// K0: bump epoch + clear span counters. One block (pure launch-latency cost).
// ---------------------------------------------------------------------------
__global__ void reset_kernel() {
    if (threadIdx.x == 0) g_epoch = g_epoch % 32767u + 1u;  // 1..32767, never 0
    ((uint4*)g_cnt)[threadIdx.x] = make_uint4(0, 0, 0, 0);  // 256 thr x 4
}

// ---------------------------------------------------------------------------
// K1: build per-cell chains + per-span touched lists (proven round-7 form:
// atomicExch on slots, plain atomicAdd on pre-cleared counters).
// ---------------------------------------------------------------------------
__global__ void claim_kernel(const int* __restrict__ coord,
                             const int* __restrict__ contains) {
    unsigned bp = blockIdx.x * blockDim.x + threadIdx.x;
    if (bp >= BP_TOTAL) return;
    if (contains[bp] != 1) return;

    const unsigned e = g_epoch;                  // uniform broadcast load
    const unsigned b = bp / P;
    const int y = coord[bp * 3 + 1];
    const int x = coord[bp * 3 + 2];
    const unsigned cell = (unsigned)(y * XS + x);

    unsigned old = atomicExch(&g_slot[b * CELLS + cell], (e << 17) | (bp + 1u));
    bool fresh = (old >> 17) == e;               // cell already claimed this call?
    g_next[bp] = fresh ? (int)(old & 0x1FFFFu) - 1 : -1;

    if (!fresh) {                                // first claimant: register cell
        unsigned span = b * SPANS + (cell >> 10);
        unsigned pos = atomicAdd(&g_cnt[span], 1u);
        if (pos < LIST_MAX)
            g_list[span * LIST_MAX + pos] = (int)cell;
    }
}

// ---------------------------------------------------------------------------
// K2: zero + fixup, linear geometry, 32 KB chunks.
// Block = (b, f, chunk) with chunk fastest => block id order == address
// order. Chunk = 8192 cells = 8 spans at one plane.
//   - tid<8 loads the 8 span counts into smem; every thread prefetches two
//     list entries (entries tid and tid+256 of the 8x64 grid) — all hidden
//     under the store stream
//   - 8 strided float4 zero stores per thread (8-deep store MLP)
//   - __syncthreads, then ~187 valid entries resolve: slot head ->
//     chain walk over pillars[p*64+f] -> 4B overwrite on a just-written line
// ---------------------------------------------------------------------------
__global__ void fused_kernel(const float* __restrict__ pillars,
                             float* __restrict__ out) {
    __shared__ unsigned s_n[8];

    const unsigned blk   = blockIdx.x;           // 0..8191
    const unsigned tid   = threadIdx.x;          // 0..255
    const unsigned b     = blk >> 11;
    const unsigned f     = (blk >> 5) & 63;
    const unsigned chunk = blk & 31;             // 32 chunks per plane
    const unsigned sp0   = b * SPANS + (chunk << 3);   // first of 8 spans

    // Early independent loads (retire under the store stream)
    if (tid < 8) s_n[tid] = g_cnt[sp0 + tid];
    const unsigned s0 = tid >> 6;                // entry tid:     span 0..3
    const unsigned s1 = s0 + 4;                  // entry tid+256: span 4..7
    const unsigned j  = tid & 63;                // list slot (0..63)
    int cellA = g_list[(sp0 + s0) * LIST_MAX + j];   // prefetch (maybe unused)
    int cellB = g_list[(sp0 + s1) * LIST_MAX + j];

    // Linear zero stores: 8 strided float4 per thread = contiguous 32 KB/block
    float4* base = (float4*)out + (blk << 11);
    const float4 z = make_float4(0.f, 0.f, 0.f, 0.f);
    #pragma unroll
    for (int k = 0; k < 8; ++k)
        base[tid + (k << 8)] = z;

    __syncthreads();   // counts visible + zero-stores ordered before fixups

    const unsigned planeBase = (b * NF + f) << 18;

    if (j < s_n[s0]) {
        unsigned head = g_slot[b * CELLS + (unsigned)cellA];
        int p = (int)(head & 0x1FFFFu) - 1;
        float acc = 0.f;
        while (p >= 0) {                         // chain length ~1
            acc += pillars[(unsigned)p * NF + f];
            p = g_next[p];
        }
        out[planeBase + (unsigned)cellA] = acc;
    }
    if (j < s_n[s1]) {
        unsigned head = g_slot[b * CELLS + (unsigned)cellB];
        int p = (int)(head & 0x1FFFFu) - 1;
        float acc = 0.f;
        while (p >= 0) {
            acc += pillars[(unsigned)p * NF + f];
            p = g_next[p];
        }
        out[planeBase + (unsigned)cellB] = acc;
    }

    // Overflow (>64 touched in one span): essentially never (P ~ 1e-13)
    #pragma unroll
    for (unsigned ss = 0; ss < 2; ++ss) {
        const unsigned s = ss ? s1 : s0;
        const unsigned n = s_n[s];
        for (unsigned jj = j + 64; jj < n && jj < LIST_MAX; jj += 64) {
            int c2 = g_list[(sp0 + s) * LIST_MAX + jj];
            unsigned head = g_slot[b * CELLS + (unsigned)c2];
            int p = (int)(head & 0x1FFFFu) - 1;
            float acc = 0.f;
            while (p >= 0) {
                acc += pillars[(unsigned)p * NF + f];
                p = g_next[p];
            }
            out[planeBase + (unsigned)c2] = acc;
        }
    }
}

extern "C" void kernel_launch(void* const* d_in, const int* in_sizes, int n_in,
                              void* d_out, int out_size) {
    const float* pillars  = (const float*)d_in[0];  // [B, P, NF] fp32
    const int*   coord    = (const int*)  d_in[1];  // [B, P, 3]  int32
    const int*   contains = (const int*)  d_in[2];  // [B, P]     int32
    float*       out      = (float*)d_out;          // [B, NF, XS, YS] fp32

    reset_kernel<<<1, 256>>>();                                  // 1024 counters
    claim_kernel<<<(BP_TOTAL + 255) / 256, 256>>>(coord, contains);
    fused_kernel<<<B * NF * CHUNKS, 256>>>(pillars, out);        // 8192 blocks
}

// round 12
// speedup vs baseline: 1.0360x; 1.0360x over previous
#include <cuda_runtime.h>

// Problem constants (fixed by the dataset)
#define B   4
#define P   12000
#define NF  64
#define XS  512
#define YS  512
#define CELLS    (XS * YS)                // 262144 per batch
#define BP_TOTAL (B * P)                  // 48000
#define SPANS    256                      // 1024-cell spans per batch
#define NSPAN    (B * SPANS)              // 1024
#define LIST_MAX 128                      // >> mean 23.4 touched/span
#define CHUNKS   64                       // 16KB chunks per plane (4 spans each)

// Epoch-tagged slot map: slot value = (e<<17) | (bp+1), e in [1,32767].
// Effective epoch e = g_epoch + 1. All state is CUDA zero-initialized and
// SELF-MAINTAINED across calls:
//   - g_cnt is cleared for the next call by the 64th (last) fused-block
//     reader of each span (per-span ticket in g_tick, distinct addresses)
//   - the last span-winner (1024 of them, one g_done address) bumps g_epoch
// -> NO reset kernel, fully graph-replay-safe.
__device__ unsigned g_epoch;                      // effective e = this + 1
__device__ unsigned g_done;                       // span-winner ticket (0..1023)
__device__ unsigned g_slot[B * CELLS];            // 4 MB
__device__ int      g_next[BP_TOTAL];             // chain next, -1 terminated
__device__ unsigned g_cnt[NSPAN];                 // touched cells per span
__device__ unsigned g_tick[NSPAN];                // per-span reader tickets
__device__ int      g_list[NSPAN * LIST_MAX];     // touched cell ids (512 KB)

// ---------------------------------------------------------------------------
// K1: build per-cell chains + per-span touched lists.
// atomicExch on slots, plain atomicAdd on counters (cleared by previous call).
// ---------------------------------------------------------------------------
__global__ void claim_kernel(const int* __restrict__ coord,
                             const int* __restrict__ contains) {
    unsigned bp = blockIdx.x * blockDim.x + threadIdx.x;
    if (bp >= BP_TOTAL) return;
    if (contains[bp] != 1) return;

    const unsigned e = g_epoch + 1u;             // uniform broadcast load
    const unsigned b = bp / P;
    const int y = coord[bp * 3 + 1];
    const int x = coord[bp * 3 + 2];
    const unsigned cell = (unsigned)(y * XS + x);

    unsigned old = atomicExch(&g_slot[b * CELLS + cell], (e << 17) | (bp + 1u));
    bool fresh = (old >> 17) == e;               // cell already claimed this call?
    g_next[bp] = fresh ? (int)(old & 0x1FFFFu) - 1 : -1;

    if (!fresh) {                                // first claimant: register cell
        unsigned span = b * SPANS + (cell >> 10);
        unsigned pos = atomicAdd(&g_cnt[span], 1u);
        if (pos < LIST_MAX)
            g_list[span * LIST_MAX + pos] = (int)cell;
    }
}

// ---------------------------------------------------------------------------
// K2: zero + fixup, linear geometry, 16 KB chunks (round-10 proven best).
// Block = (b, f, chunk) with chunk fastest => block id order == address
// order. Chunk = 4096 cells = 4 spans at one plane.
//   - tid<4 loads the 4 span counts; every thread prefetches one list entry
//     (span tid>>6, slot tid&63) — hidden under the store stream
//   - 4 strided float4 zero stores per thread
//   - __syncthreads, fixups overwrite just-written lines
//   - epilogue: per-span reader tickets clear counters for the NEXT call;
//     the last span-winner bumps the epoch.
// ---------------------------------------------------------------------------
__global__ void fused_kernel(const float* __restrict__ pillars,
                             float* __restrict__ out) {
    __shared__ unsigned s_n[4];

    const unsigned blk   = blockIdx.x;           // 0..16383
    const unsigned tid   = threadIdx.x;          // 0..255
    const unsigned b     = blk >> 12;
    const unsigned f     = (blk >> 6) & 63;
    const unsigned chunk = blk & 63;             // 64 chunks per plane
    const unsigned sp0   = b * SPANS + (chunk << 2);   // first of 4 spans

    // Early independent loads (retire under the store stream)
    if (tid < 4) s_n[tid] = g_cnt[sp0 + tid];
    const unsigned s = tid >> 6;                 // span within chunk (0..3)
    const unsigned j = tid & 63;                 // list slot (0..63)
    int cell = g_list[(sp0 + s) * LIST_MAX + j]; // prefetch (maybe unused)

    // Linear zero stores: 4 strided float4 per thread = contiguous 16 KB/block
    float4* base = (float4*)out + (blk << 10);
    const float4 z = make_float4(0.f, 0.f, 0.f, 0.f);
    base[tid      ] = z;
    base[tid + 256] = z;
    base[tid + 512] = z;
    base[tid + 768] = z;

    __syncthreads();   // counts visible + zero-stores ordered before fixups

    const unsigned n = s_n[s];
    const unsigned planeBase = (b * NF + f) << 18;
    if (j < n) {
        unsigned head = g_slot[b * CELLS + (unsigned)cell];  // fresh this call
        int p = (int)(head & 0x1FFFFu) - 1;
        float acc = 0.f;
        while (p >= 0) {                                     // chain length ~1
            acc += pillars[(unsigned)p * NF + f];
            p = g_next[p];
        }
        out[planeBase + (unsigned)cell] = acc;
    }
    // Overflow (>64 touched in one span): essentially never (P ~ 1e-13)
    for (unsigned jj = j + 64; jj < n && jj < LIST_MAX; jj += 64) {
        int c2 = g_list[(sp0 + s) * LIST_MAX + jj];
        unsigned head = g_slot[b * CELLS + (unsigned)c2];
        int p = (int)(head & 0x1FFFFu) - 1;
        float acc = 0.f;
        while (p >= 0) {
            acc += pillars[(unsigned)p * NF + f];
            p = g_next[p];
        }
        out[planeBase + (unsigned)c2] = acc;
    }

    // Epilogue: self-maintenance for the next call.
    // This thread's counter load has long retired (value consumed above), so
    // ticketing here proves all 64 readers of a span are done before clearing.
    if (tid < 4) {
        unsigned t = atomicAdd(&g_tick[sp0 + tid], 1u);
        if (t == 63u) {                          // last reader of this span
            g_cnt[sp0 + tid]  = 0u;              // clear for next call
            g_tick[sp0 + tid] = 0u;              // rearm ticket
            unsigned d = atomicAdd(&g_done, 1u); // 1024 winners, one address
            if (d == NSPAN - 1u) {               // the very last winner
                g_done  = 0u;
                g_epoch = (g_epoch + 1u) % 32767u;  // next e in [1,32767]
            }
        }
    }
}

extern "C" void kernel_launch(void* const* d_in, const int* in_sizes, int n_in,
                              void* d_out, int out_size) {
    const float* pillars  = (const float*)d_in[0];  // [B, P, NF] fp32
    const int*   coord    = (const int*)  d_in[1];  // [B, P, 3]  int32
    const int*   contains = (const int*)  d_in[2];  // [B, P]     int32
    float*       out      = (float*)d_out;          // [B, NF, XS, YS] fp32

    claim_kernel<<<(BP_TOTAL + 255) / 256, 256>>>(coord, contains);
    fused_kernel<<<B * NF * CHUNKS, 256>>>(pillars, out);   // 16384 blocks
}

// round 13
// speedup vs baseline: 1.1024x; 1.0642x over previous
#include <cuda_runtime.h>

// Problem constants (fixed by the dataset)
#define B   4
#define P   12000
#define NF  64
#define XS  512
#define YS  512
#define CELLS    (XS * YS)                // 262144 per batch
#define BP_TOTAL (B * P)                  // 48000
#define SPANS    256                      // 1024-cell spans per batch
#define NSPAN    (B * SPANS)              // 1024
#define LIST_MAX 128                      // >> mean 23.4 touched/span
#define CHUNKS   64                       // 16KB chunks per plane (4 spans each)

// Epoch machinery: effective epoch e = g_epoch + 1, in [1,32767] (never 0,
// so CUDA's load-time zero-init parses as stale everywhere).
//   g_slot value = (e<<17) | (bp+1)   -- claim-internal only now
//   g_fwd  value = (e<<17) | (bp+1)   -- FORWARD chain link, epoch-tagged
//   g_list entry = int2{cell, head_bp} written by the first claimant
// All state is self-maintained across calls (per-span tickets clear counters,
// last span-winner bumps the epoch) -> no reset kernel, graph-replay-safe.
__device__ unsigned g_epoch;                      // effective e = this + 1
__device__ unsigned g_done;                       // span-winner ticket (0..1023)
__device__ unsigned g_slot[B * CELLS];            // 4 MB (claim only)
__device__ unsigned g_fwd[BP_TOTAL];              // forward links, epoch-tagged
__device__ unsigned g_cnt[NSPAN];                 // touched cells per span
__device__ unsigned g_tick[NSPAN];                // per-span reader tickets
__device__ int2     g_list[NSPAN * LIST_MAX];     // {cell, head_bp} (1 MB)

// ---------------------------------------------------------------------------
// K1: build per-cell FORWARD chains + per-span touched lists.
//   fresh claimant  -> registers {cell, bp} in the span list (chain head)
//   later claimant  -> links g_fwd[prev] = (e<<17)|(bp+1)
// Walker (fused) reaches every claimant: head -> fwd -> fwd -> stale-tag stop.
// ---------------------------------------------------------------------------
__global__ void claim_kernel(const int* __restrict__ coord,
                             const int* __restrict__ contains) {
    unsigned bp = blockIdx.x * blockDim.x + threadIdx.x;
    if (bp >= BP_TOTAL) return;
    if (contains[bp] != 1) return;

    const unsigned e = g_epoch + 1u;             // uniform broadcast load
    const unsigned b = bp / P;
    const int y = coord[bp * 3 + 1];
    const int x = coord[bp * 3 + 2];
    const unsigned cell = (unsigned)(y * XS + x);

    unsigned old = atomicExch(&g_slot[b * CELLS + cell], (e << 17) | (bp + 1u));
    if ((old >> 17) == e) {
        // collision: forward-link from the previous claimant to us
        g_fwd[(old & 0x1FFFFu) - 1u] = (e << 17) | (bp + 1u);
    } else {
        // first claimant this call: register as chain head
        unsigned span = b * SPANS + (cell >> 10);
        unsigned pos = atomicAdd(&g_cnt[span], 1u);
        if (pos < LIST_MAX)
            g_list[span * LIST_MAX + pos] = make_int2((int)cell, (int)bp);
    }
}

// ---------------------------------------------------------------------------
// K2: zero + fixup, linear geometry, 16 KB chunks (proven best).
// Block = (b, f, chunk), chunk fastest => block id order == address order.
//   - tid<4 loads span counts; every thread prefetches one int2 list entry
//     (coalesced, contains cell AND chain head -> no slot re-read)
//   - 4 strided float4 zero stores per thread
//   - __syncthreads, fixups walk forward links, overwrite just-written lines
//   - epilogue: per-span tickets clear counters; last winner bumps epoch.
// ---------------------------------------------------------------------------
__global__ void fused_kernel(const float* __restrict__ pillars,
                             float* __restrict__ out) {
    __shared__ unsigned s_n[4];

    const unsigned blk   = blockIdx.x;           // 0..16383
    const unsigned tid   = threadIdx.x;          // 0..255
    const unsigned b     = blk >> 12;
    const unsigned f     = (blk >> 6) & 63;
    const unsigned chunk = blk & 63;             // 64 chunks per plane
    const unsigned sp0   = b * SPANS + (chunk << 2);   // first of 4 spans

    // Early independent loads (retire under the store stream)
    const unsigned e = g_epoch + 1u;             // read BEFORE any bump can occur
    if (tid < 4) s_n[tid] = g_cnt[sp0 + tid];
    const unsigned s = tid >> 6;                 // span within chunk (0..3)
    const unsigned j = tid & 63;                 // list slot (0..63)
    int2 ent = g_list[(sp0 + s) * LIST_MAX + j]; // {cell, head} prefetch

    // Linear zero stores: 4 strided float4 per thread = contiguous 16 KB/block
    float4* base = (float4*)out + (blk << 10);
    const float4 z = make_float4(0.f, 0.f, 0.f, 0.f);
    base[tid      ] = z;
    base[tid + 256] = z;
    base[tid + 512] = z;
    base[tid + 768] = z;

    __syncthreads();   // counts visible + zero-stores ordered before fixups

    const unsigned n = s_n[s];
    const unsigned planeBase = (b * NF + f) << 18;
    if (j < n) {
        unsigned p = (unsigned)ent.y;            // chain head (first claimant)
        float acc = 0.f;
        for (;;) {                               // forward walk, length ~1
            acc += pillars[p * NF + f];
            unsigned w = g_fwd[p];
            if ((w >> 17) != e) break;           // stale tag = chain end
            p = (w & 0x1FFFFu) - 1u;
        }
        out[planeBase + (unsigned)ent.x] = acc;
    }
    // Overflow (>64 touched in one span): essentially never (P ~ 1e-13)
    for (unsigned jj = j + 64; jj < n && jj < LIST_MAX; jj += 64) {
        int2 e2 = g_list[(sp0 + s) * LIST_MAX + jj];
        unsigned p = (unsigned)e2.y;
        float acc = 0.f;
        for (;;) {
            acc += pillars[p * NF + f];
            unsigned w = g_fwd[p];
            if ((w >> 17) != e) break;
            p = (w & 0x1FFFFu) - 1u;
        }
        out[planeBase + (unsigned)e2.x] = acc;
    }

    // Epilogue: self-maintenance for the next call. All 64 readers of a span
    // have consumed g_cnt before ticketing (their load retired above), so the
    // 64th reader may safely clear. The bump fires only after every block has
    // ticketed -> every block already read g_epoch.
    if (tid < 4) {
        unsigned t = atomicAdd(&g_tick[sp0 + tid], 1u);
        if (t == 63u) {                          // last reader of this span
            g_cnt[sp0 + tid]  = 0u;              // clear for next call
            g_tick[sp0 + tid] = 0u;              // rearm ticket
            unsigned d = atomicAdd(&g_done, 1u); // 1024 winners, one address
            if (d == NSPAN - 1u) {               // the very last winner
                g_done  = 0u;
                g_epoch = (g_epoch + 1u) % 32767u;  // next e in [1,32767]
            }
        }
    }
}

extern "C" void kernel_launch(void* const* d_in, const int* in_sizes, int n_in,
                              void* d_out, int out_size) {
    const float* pillars  = (const float*)d_in[0];  // [B, P, NF] fp32
    const int*   coord    = (const int*)  d_in[1];  // [B, P, 3]  int32
    const int*   contains = (const int*)  d_in[2];  // [B, P]     int32
    float*       out      = (float*)d_out;          // [B, NF, XS, YS] fp32

    claim_kernel<<<(BP_TOTAL + 255) / 256, 256>>>(coord, contains);
    fused_kernel<<<B * NF * CHUNKS, 256>>>(pillars, out);   // 16384 blocks
}

// round 15
// speedup vs baseline: 1.1236x; 1.0192x over previous
#include <cuda_runtime.h>

// Problem constants (fixed by the dataset)
#define B   4
#define P   12000
#define NF  64
#define XS  512
#define YS  512
#define CELLS    (XS * YS)                // 262144 per batch
#define BP_TOTAL (B * P)                  // 48000
#define SPANS    256                      // 1024-cell spans per batch
#define NSPAN    (B * SPANS)              // 1024
#define LIST_MAX 128                      // >> mean 23.4 touched/span
#define CHUNKS   64                       // 16KB chunks per plane (4 spans each)

// Epoch machinery: effective epoch e = g_epoch + 1, in [1,32767] (never 0,
// so CUDA's load-time zero-init parses as stale everywhere).
//   g_slot value = (e<<17) | (bp+1)   -- claim-internal only
//   g_fwd  value = (e<<17) | (bp+1)   -- forward chain link, epoch-tagged
//   g_coll value = e                  -- span had >=1 collision this call
//   g_list entry = int2{cell, head_bp} written by the first claimant
// All state is self-maintained across calls (per-span tickets clear counters,
// last span-winner bumps the epoch) -> no reset kernel, graph-replay-safe.
__device__ unsigned g_epoch;                      // effective e = this + 1
__device__ unsigned g_done;                       // span-winner ticket (0..1023)
__device__ unsigned g_slot[B * CELLS];            // 4 MB (claim only)
__device__ unsigned g_fwd[BP_TOTAL];              // forward links, epoch-tagged
__device__ unsigned g_cnt[NSPAN];                 // touched cells per span
__device__ unsigned g_tick[NSPAN];                // per-span reader tickets
__device__ unsigned g_coll[NSPAN];                // collision flags, epoch-tagged
__device__ int2     g_list[NSPAN * LIST_MAX];     // {cell, head_bp} (1 MB)

// ---------------------------------------------------------------------------
// K1: build per-cell FORWARD chains + per-span touched lists.
//   fresh claimant  -> registers {cell, bp} in the span list (chain head)
//   later claimant  -> links g_fwd[prev] = (e<<17)|(bp+1) and flags the span
// ---------------------------------------------------------------------------
__global__ void claim_kernel(const int* __restrict__ coord,
                             const int* __restrict__ contains) {
    unsigned bp = blockIdx.x * blockDim.x + threadIdx.x;
    if (bp >= BP_TOTAL) return;
    if (contains[bp] != 1) return;

    const unsigned e = g_epoch + 1u;             // uniform broadcast load
    const unsigned b = bp / P;
    const int y = coord[bp * 3 + 1];
    const int x = coord[bp * 3 + 2];
    const unsigned cell = (unsigned)(y * XS + x);
    const unsigned span = b * SPANS + (cell >> 10);

    unsigned old = atomicExch(&g_slot[b * CELLS + cell], (e << 17) | (bp + 1u));
    if ((old >> 17) == e) {
        // collision: forward-link from the previous claimant to us
        g_fwd[(old & 0x1FFFFu) - 1u] = (e << 17) | (bp + 1u);
        g_coll[span] = e;                        // benign same-value race
    } else {
        // first claimant this call: register as chain head
        unsigned pos = atomicAdd(&g_cnt[span], 1u);
        if (pos < LIST_MAX)
            g_list[span * LIST_MAX + pos] = make_int2((int)cell, (int)bp);
    }
}

// ---------------------------------------------------------------------------
// K2: zero + fixup, linear geometry, 16 KB chunks (proven best).
// Block = (b, f, chunk), chunk fastest => block id order == address order.
//   - tid<4 loads span counts + collision flags; every thread prefetches one
//     int2 list entry (cell AND chain head) — all under the store stream
//   - 4 strided float4 zero stores per thread
//   - __syncthreads, fixups: warp-uniform fast path (no g_fwd load) for
//     collision-free spans (~79%), chain walk otherwise
//   - epilogue: per-span tickets clear counters; last winner bumps epoch.
// ---------------------------------------------------------------------------
__global__ void fused_kernel(const float* __restrict__ pillars,
                             float* __restrict__ out) {
    __shared__ unsigned s_n[4];
    __shared__ unsigned s_c[4];

    const unsigned blk   = blockIdx.x;           // 0..16383
    const unsigned tid   = threadIdx.x;          // 0..255
    const unsigned b     = blk >> 12;
    const unsigned f     = (blk >> 6) & 63;
    const unsigned chunk = blk & 63;             // 64 chunks per plane
    const unsigned sp0   = b * SPANS + (chunk << 2);   // first of 4 spans

    // Early independent loads (retire under the store stream)
    const unsigned e = g_epoch + 1u;             // read BEFORE any bump can occur
    if (tid < 4) {
        s_n[tid] = g_cnt[sp0 + tid];
        s_c[tid] = g_coll[sp0 + tid];
    }
    const unsigned s = tid >> 6;                 // span within chunk (warp-uniform)
    const unsigned j = tid & 63;                 // list slot (0..63)
    int2 ent = g_list[(sp0 + s) * LIST_MAX + j]; // {cell, head} prefetch

    // Linear zero stores: 4 strided float4 per thread = contiguous 16 KB/block
    float4* base = (float4*)out + (blk << 10);
    const float4 z = make_float4(0.f, 0.f, 0.f, 0.f);
    base[tid      ] = z;
    base[tid + 256] = z;
    base[tid + 512] = z;
    base[tid + 768] = z;

    __syncthreads();   // counts visible + zero-stores ordered before fixups

    const unsigned n = s_n[s];
    const bool has_coll = (s_c[s] == e);         // warp-uniform branch
    const unsigned planeBase = (b * NF + f) << 18;

    if (j < n) {
        unsigned p = (unsigned)ent.y;            // chain head (first claimant)
        float acc;
        if (!has_coll) {
            acc = pillars[p * NF + f];           // fast path: no g_fwd access
        } else {
            acc = 0.f;
            for (;;) {                           // forward walk, length ~1-2
                acc += pillars[p * NF + f];
                unsigned w = g_fwd[p];
                if ((w >> 17) != e) break;       // stale tag = chain end
                p = (w & 0x1FFFFu) - 1u;
            }
        }
        out[planeBase + (unsigned)ent.x] = acc;
    }
    // Overflow (>64 touched in one span): essentially never (P ~ 1e-13)
    for (unsigned jj = j + 64; jj < n && jj < LIST_MAX; jj += 64) {
        int2 e2 = g_list[(sp0 + s) * LIST_MAX + jj];
        unsigned p = (unsigned)e2.y;
        float acc = 0.f;
        for (;;) {
            acc += pillars[p * NF + f];
            unsigned w = g_fwd[p];
            if ((w >> 17) != e) break;
            p = (w & 0x1FFFFu) - 1u;
        }
        out[planeBase + (unsigned)e2.x] = acc;
    }

    // Epilogue: self-maintenance for the next call (g_coll needs no clearing,
    // it is epoch-tagged). All 64 readers of a span have consumed g_cnt before
    // ticketing, so the 64th reader may safely clear.
    if (tid < 4) {
        unsigned t = atomicAdd(&g_tick[sp0 + tid], 1u);
        if (t == 63u) {                          // last reader of this span
            g_cnt[sp0 + tid]  = 0u;              // clear for next call
            g_tick[sp0 + tid] = 0u;              // rearm ticket
            unsigned d = atomicAdd(&g_done, 1u); // 1024 winners, one address
            if (d == NSPAN - 1u) {               // the very last winner
                g_done  = 0u;
                g_epoch = (g_epoch + 1u) % 32767u;  // next e in [1,32767]
            }
        }
    }
}

extern "C" void kernel_launch(void* const* d_in, const int* in_sizes, int n_in,
                              void* d_out, int out_size) {
    const float* pillars  = (const float*)d_in[0];  // [B, P, NF] fp32
    const int*   coord    = (const int*)  d_in[1];  // [B, P, 3]  int32
    const int*   contains = (const int*)  d_in[2];  // [B, P]     int32
    float*       out      = (float*)d_out;          // [B, NF, XS, YS] fp32

    claim_kernel<<<(BP_TOTAL + 255) / 256, 256>>>(coord, contains);
    fused_kernel<<<B * NF * CHUNKS, 256>>>(pillars, out);   // 16384 blocks
}

// round 16
// speedup vs baseline: 1.1242x; 1.0006x over previous
#include <cuda_runtime.h>

// Problem constants (fixed by the dataset)
#define B   4
#define P   12000
#define NF  64
#define XS  512
#define YS  512
#define CELLS    (XS * YS)                // 262144 per batch
#define BP_TOTAL (B * P)                  // 48000
#define SPANS    256                      // 1024-cell spans per batch
#define NSPAN    (B * SPANS)              // 1024
#define LIST_MAX 128                      // >> mean 23.4 touched/span
#define CHUNKS   64                       // 16KB chunks per plane (4 spans each)

// Epoch machinery: effective epoch e = g_epoch + 1, in [1,32767] (never 0,
// so CUDA's load-time zero-init parses as stale everywhere).
//   g_slot value = (e<<17) | (bp+1)   -- claim-internal only
//   g_fwd  value = (e<<17) | (bp+1)   -- forward chain link, epoch-tagged
//   g_cnt  value = count | (collision ? 1u<<31 : 0)  -- cleared every call
//   g_list entry = int2{cell, head_bp} written by the first claimant
// All state is self-maintained across calls (per-span tickets clear counters,
// last span-winner bumps the epoch) -> no reset kernel, graph-replay-safe.
__device__ unsigned g_epoch;                      // effective e = this + 1
__device__ unsigned g_done;                       // span-winner ticket (0..1023)
__device__ unsigned g_slot[B * CELLS];            // 4 MB (claim only)
__device__ unsigned g_fwd[BP_TOTAL];              // forward links, epoch-tagged
__device__ unsigned g_cnt[NSPAN];                 // count + collision flag
__device__ unsigned g_tick[NSPAN];                // per-span reader tickets
__device__ int2     g_list[NSPAN * LIST_MAX];     // {cell, head_bp} (1 MB)

// ---------------------------------------------------------------------------
// K1: build per-cell FORWARD chains + per-span touched lists.
// Triggers the dependent fused launch IMMEDIATELY (PDL): fused's zero-store
// phase overlaps this kernel; fused reads our outputs only after
// cudaGridDependencySynchronize().
// ---------------------------------------------------------------------------
__global__ void claim_kernel(const int* __restrict__ coord,
                             const int* __restrict__ contains) {
    cudaTriggerProgrammaticLaunchCompletion();   // let fused launch now

    unsigned bp = blockIdx.x * blockDim.x + threadIdx.x;
    if (bp >= BP_TOTAL) return;
    if (contains[bp] != 1) return;

    const unsigned e = g_epoch + 1u;             // uniform broadcast load
    const unsigned b = bp / P;
    const int y = coord[bp * 3 + 1];
    const int x = coord[bp * 3 + 2];
    const unsigned cell = (unsigned)(y * XS + x);
    const unsigned span = b * SPANS + (cell >> 10);

    unsigned old = atomicExch(&g_slot[b * CELLS + cell], (e << 17) | (bp + 1u));
    if ((old >> 17) == e) {
        // collision: forward-link from the previous claimant to us + flag span
        g_fwd[(old & 0x1FFFFu) - 1u] = (e << 17) | (bp + 1u);
        atomicOr(&g_cnt[span], 1u << 31);
    } else {
        // first claimant this call: register as chain head
        unsigned pos = atomicAdd(&g_cnt[span], 1u) & 0x7FFFFFFFu;
        if (pos < LIST_MAX)
            g_list[span * LIST_MAX + pos] = make_int2((int)cell, (int)bp);
    }
}

// ---------------------------------------------------------------------------
// K2: zero + fixup, linear geometry, 16 KB chunks (proven best), PDL secondary.
// Block = (b, f, chunk), chunk fastest => block id order == address order.
//   - 4 strided float4 zero stores per thread (independent of claim)
//   - cudaGridDependencySynchronize(): waits for claim (no-op after wave 1)
//   - load span counts+flags, prefetch list entries (j<32; tail rare)
//   - __syncthreads, fixups overwrite just-written lines (warp-uniform
//     no-collision fast path avoids all g_fwd loads)
//   - epilogue: per-span tickets clear counters; last winner bumps epoch.
// ---------------------------------------------------------------------------
__global__ void fused_kernel(const float* __restrict__ pillars,
                             float* __restrict__ out) {
    __shared__ unsigned s_n[4];

    const unsigned blk   = blockIdx.x;           // 0..16383
    const unsigned tid   = threadIdx.x;          // 0..255
    const unsigned b     = blk >> 12;
    const unsigned f     = (blk >> 6) & 63;
    const unsigned chunk = blk & 63;             // 64 chunks per plane
    const unsigned sp0   = b * SPANS + (chunk << 2);   // first of 4 spans

    const unsigned e = g_epoch + 1u;             // written only by PREVIOUS
                                                 // fused call (stream-ordered)

    // Linear zero stores: 4 strided float4 per thread = contiguous 16 KB/block.
    // Touches only `out` -> safe while claim is still running.
    float4* base = (float4*)out + (blk << 10);
    const float4 z = make_float4(0.f, 0.f, 0.f, 0.f);
    base[tid      ] = z;
    base[tid + 256] = z;
    base[tid + 512] = z;
    base[tid + 768] = z;

    // Wait for claim's grid (memory-visible). Instant for waves >= 2.
    cudaGridDependencySynchronize();

    if (tid < 4) s_n[tid] = g_cnt[sp0 + tid];
    const unsigned s = tid >> 6;                 // span within chunk (warp-uniform)
    const unsigned j = tid & 63;                 // list slot (0..63)
    int2 ent = make_int2(0, 0);
    if (j < 32) ent = g_list[(sp0 + s) * LIST_MAX + j];  // bulk prefetch

    __syncthreads();   // counts visible + zero-stores ordered before fixups

    const unsigned cw = s_n[s];
    const unsigned n = cw & 0x7FFFFFFFu;
    const bool has_coll = (cw >> 31) != 0u;      // warp-uniform branch
    const unsigned planeBase = (b * NF + f) << 18;

    if (j < n) {
        int2 E = (j < 32) ? ent : g_list[(sp0 + s) * LIST_MAX + j];  // tail rare
        unsigned p = (unsigned)E.y;              // chain head (first claimant)
        float acc;
        if (!has_coll) {
            acc = pillars[p * NF + f];           // fast path: no g_fwd access
        } else {
            acc = 0.f;
            for (;;) {                           // forward walk, length ~1-2
                acc += pillars[p * NF + f];
                unsigned w = g_fwd[p];
                if ((w >> 17) != e) break;       // stale tag = chain end
                p = (w & 0x1FFFFu) - 1u;
            }
        }
        out[planeBase + (unsigned)E.x] = acc;
    }
    // Overflow (>64 touched in one span): essentially never (P ~ 1e-13)
    for (unsigned jj = j + 64; jj < n && jj < LIST_MAX; jj += 64) {
        int2 E2 = g_list[(sp0 + s) * LIST_MAX + jj];
        unsigned p = (unsigned)E2.y;
        float acc = 0.f;
        for (;;) {
            acc += pillars[p * NF + f];
            unsigned w = g_fwd[p];
            if ((w >> 17) != e) break;
            p = (w & 0x1FFFFu) - 1u;
        }
        out[planeBase + (unsigned)E2.x] = acc;
    }

    // Epilogue: self-maintenance for the next call. All 64 readers of a span
    // have consumed g_cnt before ticketing, so the 64th reader safely clears.
    if (tid < 4) {
        unsigned t = atomicAdd(&g_tick[sp0 + tid], 1u);
        if (t == 63u) {                          // last reader of this span
            g_cnt[sp0 + tid]  = 0u;              // clear count + collision flag
            g_tick[sp0 + tid] = 0u;              // rearm ticket
            unsigned d = atomicAdd(&g_done, 1u); // 1024 winners, one address
            if (d == NSPAN - 1u) {               // the very last winner
                g_done  = 0u;
                g_epoch = (g_epoch + 1u) % 32767u;  // next e in [1,32767]
            }
        }
    }
}

extern "C" void kernel_launch(void* const* d_in, const int* in_sizes, int n_in,
                              void* d_out, int out_size) {
    const float* pillars  = (const float*)d_in[0];  // [B, P, NF] fp32
    const int*   coord    = (const int*)  d_in[1];  // [B, P, 3]  int32
    const int*   contains = (const int*)  d_in[2];  // [B, P]     int32
    float*       out      = (float*)d_out;          // [B, NF, XS, YS] fp32

    // K1: normal launch
    claim_kernel<<<(BP_TOTAL + 255) / 256, 256>>>(coord, contains);

    // K2: PDL secondary — launches while claim runs; device-side
    // cudaGridDependencySynchronize() provides the ordering.
    cudaLaunchConfig_t cfg = {};
    cfg.gridDim  = dim3(B * NF * CHUNKS);           // 16384 blocks
    cfg.blockDim = dim3(256);
    cfg.stream   = 0;                               // same (legacy) stream
    cudaLaunchAttribute attr[1];
    attr[0].id = cudaLaunchAttributeProgrammaticStreamSerialization;
    attr[0].val.programmaticStreamSerializationAllowed = 1;
    cfg.attrs = attr;
    cfg.numAttrs = 1;
    cudaLaunchKernelEx(&cfg, fused_kernel, pillars, out);
}